// round 5
// baseline (speedup 1.0000x reference)
#include <cuda_runtime.h>
#include <cuda_bf16.h>
#include <cstdint>
#include <cstddef>

#define DEV __device__ __forceinline__

// ---------------- problem dims ----------------
#define DDIM 1024
#define HDIM 4096
#define MM   16384
#define N1  ((long long)MM * DDIM)        // 16,777,216
#define N2  ((long long)MM * HDIM)        // 67,108,864
#define NW1 ((long long)HDIM * DDIM)
#define NW2 ((long long)DDIM * HDIM)
#define RANK1 16693329LL                  // nearest-rank 0.995 quantile over N1

// ---------------- device scratch ----------------
__device__ float        g_h1 [(size_t)N1];     // LN output fp32
__device__ signed char  g_h1q[(size_t)N1];     // int8 acts layer1
__device__ short        g_n2 [(size_t)N2];     // GEMM1 integer output (exact)
__device__ signed char  g_a2q[(size_t)N2];     // int8 acts layer2
__device__ signed char  g_w1q[(size_t)NW1];    // ternary w1
__device__ signed char  g_w2q[(size_t)NW2];    // ternary w2
__device__ unsigned     g_hist2[65536];        // hist of n (offset +32768)
__device__ signed char  g_lut[65536];          // n -> quantized gelu int8

__device__ unsigned  g_bins[2048];
__device__ unsigned  g_prefix, g_prefmask;
__device__ long long g_rank;
__device__ float     g_s[2];        // s = 127/amax
__device__ float     g_gamma[2];    // gamma = mean|w| + 1e-5
__device__ float     g_sc1;         // gamma1/s1
__device__ double    g_wpart[2][512];

// ---------------- helpers ----------------
DEV float ff_warp_sum(float v) {
    #pragma unroll
    for (int o = 16; o; o >>= 1) v += __shfl_xor_sync(0xffffffffu, v, o);
    return v;
}
DEV float ff_gelu(float x) {
    return 0.5f * x * (1.0f + erff(x * 0.70710678118654752440f));
}
DEV uint32_t ff_smem_u32(const void* p) {
    uint32_t a;
    asm("{ .reg .u64 t; cvta.to.shared.u64 t, %1; cvt.u32.u64 %0, t; }" : "=r"(a) : "l"(p));
    return a;
}
DEV void ff_cp_async16(uint32_t sdst, const void* gsrc) {
    asm volatile("cp.async.cg.shared.global [%0], [%1], 16;\n" :: "r"(sdst), "l"(gsrc));
}
DEV int ff_q8(float x, float s) {   // round-clip to [-128,127]
    return (int)fminf(fmaxf(rintf(x * s), -128.0f), 127.0f);
}
DEV unsigned ff_pack4(int a, int b, int c, int d) {
    return (unsigned)(a & 0xff) | ((unsigned)(b & 0xff) << 8) |
           ((unsigned)(c & 0xff) << 16) | ((unsigned)(d & 0xff) << 24);
}

// ---------------- layernorm ----------------
__global__ __launch_bounds__(256) void ff_ln_kernel(
    const float* __restrict__ x, const float* __restrict__ gam,
    const float* __restrict__ bet)
{
    int row = blockIdx.x;
    int tid = threadIdx.x, w = tid >> 5, l = tid & 31;
    const float4* xr = (const float4*)(x + (size_t)row * DDIM);
    float4 v = xr[tid];

    __shared__ float sh[8];
    __shared__ float s_mu, s_inv;

    float s = v.x + v.y + v.z + v.w;
    float ws = ff_warp_sum(s);
    if (l == 0) sh[w] = ws;
    __syncthreads();
    if (w == 0) {
        float a = (l < 8) ? sh[l] : 0.0f;
        a = ff_warp_sum(a);
        if (l == 0) s_mu = a * (1.0f / DDIM);
    }
    __syncthreads();
    float mu = s_mu;

    float dx = v.x - mu, dy = v.y - mu, dz = v.z - mu, dw = v.w - mu;
    float ss = dx*dx + dy*dy + dz*dz + dw*dw;
    float wss = ff_warp_sum(ss);
    __syncthreads();
    if (l == 0) sh[w] = wss;
    __syncthreads();
    if (w == 0) {
        float a = (l < 8) ? sh[l] : 0.0f;
        a = ff_warp_sum(a);
        if (l == 0) s_inv = 1.0f / sqrtf(a * (1.0f / DDIM) + 1e-5f);
    }
    __syncthreads();
    float inv = s_inv;

    float4 g4 = ((const float4*)gam)[tid], b4 = ((const float4*)bet)[tid];
    float4 o;
    o.x = dx * inv * g4.x + b4.x;
    o.y = dy * inv * g4.y + b4.y;
    o.z = dz * inv * g4.z + b4.z;
    o.w = dw * inv * g4.w + b4.w;
    ((float4*)(g_h1 + (size_t)row * DDIM))[tid] = o;
}

// ---------------- weight gamma + ternary quantize (int8) ----------------
__global__ __launch_bounds__(256) void ff_wabs_part(const float* __restrict__ w,
                                                    long long n, int idx)
{
    long long per = n / gridDim.x;
    long long s0 = (long long)blockIdx.x * per;
    double acc = 0.0;
    for (long long i = s0 + threadIdx.x; i < s0 + per; i += blockDim.x)
        acc += (double)fabsf(w[i]);
    __shared__ double sd[256];
    sd[threadIdx.x] = acc;
    __syncthreads();
    for (int o = 128; o; o >>= 1) {
        if (threadIdx.x < o) sd[threadIdx.x] += sd[threadIdx.x + o];
        __syncthreads();
    }
    if (threadIdx.x == 0) g_wpart[idx][blockIdx.x] = sd[0];
}

__global__ void ff_wgamma_final(long long n, int idx) {
    if (threadIdx.x == 0) {
        double s = 0.0;
        for (int i = 0; i < 512; i++) s += g_wpart[idx][i];
        g_gamma[idx] = (float)(s / (double)n) + 1e-5f;
    }
}

__global__ __launch_bounds__(256) void ff_wquant(const float* __restrict__ w,
                                                 long long n4, int idx)
{
    float g = g_gamma[idx];
    unsigned* out = (unsigned*)(idx ? g_w2q : g_w1q);
    long long stride = (long long)gridDim.x * blockDim.x;
    const float4* p = (const float4*)w;
    for (long long i = (long long)blockIdx.x * blockDim.x + threadIdx.x; i < n4; i += stride) {
        float4 v = p[i];
        int t0 = (int)fminf(fmaxf(rintf(v.x / g), -1.0f), 1.0f);
        int t1 = (int)fminf(fmaxf(rintf(v.y / g), -1.0f), 1.0f);
        int t2 = (int)fminf(fmaxf(rintf(v.z / g), -1.0f), 1.0f);
        int t3 = (int)fminf(fmaxf(rintf(v.w / g), -1.0f), 1.0f);
        out[i] = ff_pack4(t0, t1, t2, t3);
    }
}

// ---------------- layer-1 radix select over |g_h1| ----------------
__global__ void ff_init_select(long long rank) {
    if (threadIdx.x == 0) { g_rank = rank; g_prefix = 0u; g_prefmask = 0u; }
    for (int i = threadIdx.x; i < 2048; i += blockDim.x) g_bins[i] = 0u;
}

__global__ __launch_bounds__(256) void ff_hist(long long n4, int shift, unsigned binmask) {
    __shared__ unsigned sb[2048];
    for (int i = threadIdx.x; i < 2048; i += blockDim.x) sb[i] = 0u;
    __syncthreads();
    unsigned pref = g_prefix, pmask = g_prefmask;
    const float4* p = (const float4*)(const float*)g_h1;
    long long stride = (long long)gridDim.x * blockDim.x;
    for (long long i = (long long)blockIdx.x * blockDim.x + threadIdx.x; i < n4; i += stride) {
        float4 v = p[i];
        unsigned u;
        u = __float_as_uint(fabsf(v.x)); if ((u & pmask) == pref) atomicAdd(&sb[(u >> shift) & binmask], 1u);
        u = __float_as_uint(fabsf(v.y)); if ((u & pmask) == pref) atomicAdd(&sb[(u >> shift) & binmask], 1u);
        u = __float_as_uint(fabsf(v.z)); if ((u & pmask) == pref) atomicAdd(&sb[(u >> shift) & binmask], 1u);
        u = __float_as_uint(fabsf(v.w)); if ((u & pmask) == pref) atomicAdd(&sb[(u >> shift) & binmask], 1u);
    }
    __syncthreads();
    for (int i = threadIdx.x; i < 2048; i += blockDim.x)
        if (sb[i]) atomicAdd(&g_bins[i], sb[i]);
}

__global__ void ff_scan(int shift, int nbins, int is_final, int sidx) {
    if (threadIdx.x == 0) {
        long long r = g_rank, cum = 0;
        int sel = nbins - 1;
        for (int b = 0; b < nbins; b++) {
            unsigned c = g_bins[b];
            if (cum + (long long)c > r) { sel = b; g_rank = r - cum; break; }
            cum += c;
        }
        unsigned pref = g_prefix | ((unsigned)sel << shift);
        if (is_final) {
            float amax = fmaxf(__uint_as_float(pref), 1e-5f);
            g_s[sidx] = 127.0f / amax;
        } else {
            g_prefix = pref;
            g_prefmask |= ((unsigned)(nbins - 1)) << shift;
        }
    }
    __syncthreads();
    for (int i = threadIdx.x; i < 2048; i += blockDim.x) g_bins[i] = 0u;
}

// ---------------- layer-1 activation quantize -> int8 ----------------
__global__ __launch_bounds__(256) void ff_actquant1(long long n4) {
    float s = g_s[0];
    const float4* in = (const float4*)(const float*)g_h1;
    unsigned* out = (unsigned*)g_h1q;
    long long stride = (long long)gridDim.x * blockDim.x;
    for (long long i = (long long)blockIdx.x * blockDim.x + threadIdx.x; i < n4; i += stride) {
        float4 v = in[i];
        out[i] = ff_pack4(ff_q8(v.x, s), ff_q8(v.y, s), ff_q8(v.z, s), ff_q8(v.w, s));
    }
}

// ---------------- int8 tensor-core GEMM: 128x128 tile, BK=64, 3-stage ----------------
#define STGB 16384   // A 8KB + B 8KB per stage

DEV void ff_ldst(const signed char* __restrict__ A, const signed char* __restrict__ Bw,
                 int KD, int bm, int bn, int kt, unsigned char* stage, int tid)
{
    #pragma unroll
    for (int i = 0; i < 2; i++) {
        int id = tid + i * 256;            // 0..511
        int row = id >> 2, ch = id & 3;
        int sw = ch ^ ((row >> 1) & 3);
        ff_cp_async16(ff_smem_u32(stage + (row * 4 + sw) * 16),
                      A  + (size_t)(bm + row) * KD + (size_t)kt * 64 + ch * 16);
        ff_cp_async16(ff_smem_u32(stage + 8192 + (row * 4 + sw) * 16),
                      Bw + (size_t)(bn + row) * KD + (size_t)kt * 64 + ch * 16);
    }
    asm volatile("cp.async.commit_group;\n");
}

template<int LAYER>
__global__ __launch_bounds__(256, 2) void ff_gemm_i8(float* __restrict__ Cout)
{
    constexpr int KD = LAYER ? HDIM : DDIM;
    constexpr int ND = LAYER ? DDIM : HDIM;
    constexpr int KT = KD / 64;
    const signed char* A  = LAYER ? g_a2q : g_h1q;
    const signed char* Bw = LAYER ? g_w2q : g_w1q;

    __shared__ __align__(128) unsigned char smem[3 * STGB];
    const int tid = threadIdx.x, lane = tid & 31, wid = tid >> 5;
    const int wm = wid >> 2, wn = wid & 3;        // 2 x 4 warp grid, each 64x32
    const int bm = blockIdx.x * 128, bn = blockIdx.y * 128;

    int acc[4][4][4];
    #pragma unroll
    for (int a = 0; a < 4; a++)
        #pragma unroll
        for (int b = 0; b < 4; b++)
            #pragma unroll
            for (int c = 0; c < 4; c++) acc[a][b][c] = 0;

    ff_ldst(A, Bw, KD, bm, bn, 0, smem, tid);
    ff_ldst(A, Bw, KD, bm, bn, 1, smem + STGB, tid);

    for (int kt = 0; kt < KT; kt++) {
        if (kt < KT - 1) asm volatile("cp.async.wait_group 1;\n" ::: "memory");
        else             asm volatile("cp.async.wait_group 0;\n" ::: "memory");
        __syncthreads();
        if (kt + 2 < KT)
            ff_ldst(A, Bw, KD, bm, bn, kt + 2, smem + ((kt + 2) % 3) * STGB, tid);

        unsigned char* sa = smem + (kt % 3) * STGB;
        unsigned char* sb = sa + 8192;

        #pragma unroll
        for (int s = 0; s < 2; s++) {          // two k32 steps per 64B tile
            unsigned ar[4][4];
            #pragma unroll
            for (int mi = 0; mi < 4; mi++) {
                int row = wm * 64 + mi * 16 + ((lane >> 3) & 1) * 8 + (lane & 7);
                int ch  = (2 * s + (lane >> 4)) ^ ((row >> 1) & 3);
                unsigned addr = ff_smem_u32(sa + (row * 4 + ch) * 16);
                asm volatile("ldmatrix.sync.aligned.m8n8.x4.shared.b16 {%0,%1,%2,%3}, [%4];\n"
                    : "=r"(ar[mi][0]), "=r"(ar[mi][1]), "=r"(ar[mi][2]), "=r"(ar[mi][3])
                    : "r"(addr));
            }
            unsigned br[4][2];
            #pragma unroll
            for (int nj2 = 0; nj2 < 2; nj2++) {
                int row = wn * 32 + nj2 * 16 + ((lane >> 3) & 1) * 8 + (lane & 7);
                int ch  = (2 * s + (lane >> 4)) ^ ((row >> 1) & 3);
                unsigned addr = ff_smem_u32(sb + (row * 4 + ch) * 16);
                unsigned q0, q1, q2, q3;
                asm volatile("ldmatrix.sync.aligned.m8n8.x4.shared.b16 {%0,%1,%2,%3}, [%4];\n"
                    : "=r"(q0), "=r"(q1), "=r"(q2), "=r"(q3) : "r"(addr));
                br[2 * nj2][0] = q0;     br[2 * nj2][1] = q2;
                br[2 * nj2 + 1][0] = q1; br[2 * nj2 + 1][1] = q3;
            }
            #pragma unroll
            for (int mi = 0; mi < 4; mi++)
                #pragma unroll
                for (int nj = 0; nj < 4; nj++) {
                    asm volatile(
                        "mma.sync.aligned.m16n8k32.row.col.s32.s8.s8.s32 "
                        "{%0,%1,%2,%3},{%4,%5,%6,%7},{%8,%9},{%0,%1,%2,%3};\n"
                        : "+r"(acc[mi][nj][0]), "+r"(acc[mi][nj][1]),
                          "+r"(acc[mi][nj][2]), "+r"(acc[mi][nj][3])
                        : "r"(ar[mi][0]), "r"(ar[mi][1]), "r"(ar[mi][2]), "r"(ar[mi][3]),
                          "r"(br[nj][0]), "r"(br[nj][1]));
                }
        }
    }

    if (LAYER == 0) {
        // store exact integers as i16 pairs
        #pragma unroll
        for (int mi = 0; mi < 4; mi++) {
            int r0 = bm + wm * 64 + mi * 16 + (lane >> 2);
            #pragma unroll
            for (int nj = 0; nj < 4; nj++) {
                int cc = bn + wn * 32 + nj * 8 + (lane & 3) * 2;
                int c0 = min(max(acc[mi][nj][0], -32768), 32767);
                int c1 = min(max(acc[mi][nj][1], -32768), 32767);
                int c2 = min(max(acc[mi][nj][2], -32768), 32767);
                int c3 = min(max(acc[mi][nj][3], -32768), 32767);
                *(unsigned*)(g_n2 + (size_t)r0 * ND + cc) =
                    ((unsigned)(unsigned short)(short)c0) | (((unsigned)(unsigned short)(short)c1) << 16);
                *(unsigned*)(g_n2 + (size_t)(r0 + 8) * ND + cc) =
                    ((unsigned)(unsigned short)(short)c2) | (((unsigned)(unsigned short)(short)c3) << 16);
            }
        }
    } else {
        float sc = g_gamma[1] / g_s[1];
        #pragma unroll
        for (int mi = 0; mi < 4; mi++) {
            int r0 = bm + wm * 64 + mi * 16 + (lane >> 2);
            #pragma unroll
            for (int nj = 0; nj < 4; nj++) {
                int cc = bn + wn * 32 + nj * 8 + (lane & 3) * 2;
                float2 p0 = make_float2((float)acc[mi][nj][0] * sc, (float)acc[mi][nj][1] * sc);
                float2 p1 = make_float2((float)acc[mi][nj][2] * sc, (float)acc[mi][nj][3] * sc);
                *(float2*)(Cout + (size_t)r0 * ND + cc) = p0;
                *(float2*)(Cout + (size_t)(r0 + 8) * ND + cc) = p1;
            }
        }
    }
}

// ---------------- layer-2 integer histogram ----------------
__global__ void ff_h2zero() {
    g_hist2[blockIdx.x * blockDim.x + threadIdx.x] = 0u;   // 256x256
}

__global__ __launch_bounds__(256) void ff_hist2(long long n8) {
    __shared__ unsigned sb[8192];                           // n in [-4096, 4095]
    for (int i = threadIdx.x; i < 8192; i += blockDim.x) sb[i] = 0u;
    __syncthreads();
    const uint4* p = (const uint4*)g_n2;
    long long stride = (long long)gridDim.x * blockDim.x;
    for (long long i = (long long)blockIdx.x * blockDim.x + threadIdx.x; i < n8; i += stride) {
        uint4 v = p[i];
        unsigned ww[4] = {v.x, v.y, v.z, v.w};
        #pragma unroll
        for (int j = 0; j < 4; j++) {
            int n0 = (int)(short)(ww[j] & 0xffffu);
            int n1 = (int)(short)(ww[j] >> 16);
            int b0 = n0 + 4096, b1 = n1 + 4096;
            if ((unsigned)b0 < 8192u) atomicAdd(&sb[b0], 1u); else atomicAdd(&g_hist2[n0 + 32768], 1u);
            if ((unsigned)b1 < 8192u) atomicAdd(&sb[b1], 1u); else atomicAdd(&g_hist2[n1 + 32768], 1u);
        }
    }
    __syncthreads();
    for (int i = threadIdx.x; i < 8192; i += blockDim.x)
        if (sb[i]) atomicAdd(&g_hist2[i + (32768 - 4096)], sb[i]);
}

// ---------------- layer-2 quantile (interpolated, exact) + scale ----------------
__global__ void ff_scan2() {
    __shared__ long long partial[256];
    int t = threadIdx.x;
    long long c = 0;
    for (int b = t * 256; b < (t + 1) * 256; b++) c += (long long)g_hist2[b];
    partial[t] = c;
    __syncthreads();
    if (t == 0) {
        double idx = 0.995 * (double)(N2 - 1);
        long long k = (long long)idx;
        double f = idx - (double)k;
        long long cum = 0;
        int chunk = 0;
        for (; chunk < 256; chunk++) {
            if (cum + partial[chunk] > k) break;
            cum += partial[chunk];
        }
        long long r = k - cum;
        int nk = 0, nk1 = 0;
        int b = chunk * 256;
        for (;; b++) {
            long long cc = (long long)g_hist2[b];
            if (r < cc) {
                nk = b - 32768;
                if (r + 1 < cc) nk1 = nk;
                else {
                    int b2 = b + 1;
                    while (b2 < 65536 && g_hist2[b2] == 0u) b2++;
                    nk1 = (b2 < 65536) ? (b2 - 32768) : nk;
                }
                break;
            }
            r -= cc;
        }
        float sc1 = g_gamma[0] / g_s[0];
        float v0 = ff_gelu(sc1 * (float)nk);
        float v1 = ff_gelu(sc1 * (float)nk1);
        float amax = fmaxf((float)((1.0 - f) * (double)v0 + f * (double)v1), 1e-5f);
        g_s[1] = 127.0f / amax;
        g_sc1 = sc1;
    }
}

// ---------------- LUT: n -> int8 quantized gelu ----------------
__global__ void ff_lut_build() {
    int i = blockIdx.x * blockDim.x + threadIdx.x;   // 256x256 = 65536
    int n = i - 32768;
    float g = ff_gelu(g_sc1 * (float)n);
    g_lut[i] = (signed char)ff_q8(g, g_s[1]);
}

// ---------------- layer-2 quantize via LUT gather ----------------
__global__ __launch_bounds__(256) void ff_actquant2(long long n8) {
    const uint4* in = (const uint4*)g_n2;
    uint2* out = (uint2*)g_a2q;
    const signed char* lut = g_lut;
    long long stride = (long long)gridDim.x * blockDim.x;
    for (long long i = (long long)blockIdx.x * blockDim.x + threadIdx.x; i < n8; i += stride) {
        uint4 v = in[i];
        unsigned ww[4] = {v.x, v.y, v.z, v.w};
        int q[8];
        #pragma unroll
        for (int j = 0; j < 4; j++) {
            q[2 * j]     = lut[(ww[j] & 0xffffu) ^ 0x8000u];
            q[2 * j + 1] = lut[(ww[j] >> 16) ^ 0x8000u];
        }
        uint2 o;
        o.x = ff_pack4(q[0], q[1], q[2], q[3]);
        o.y = ff_pack4(q[4], q[5], q[6], q[7]);
        out[i] = o;
    }
}

// ---------------- launch ----------------
extern "C" void kernel_launch(void* const* d_in, const int* in_sizes, int n_in,
                              void* d_out, int out_size)
{
    const float* x    = (const float*)d_in[0];
    const float* ln_g = (const float*)d_in[1];
    const float* ln_b = (const float*)d_in[2];
    const float* w1   = (const float*)d_in[3];
    const float* w2   = (const float*)d_in[4];
    float* out = (float*)d_out;

    // LayerNorm
    ff_ln_kernel<<<MM, 256>>>(x, ln_g, ln_b);

    // Weight ternarization (int8)
    ff_wabs_part<<<512, 256>>>(w1, NW1, 0);
    ff_wgamma_final<<<1, 32>>>(NW1, 0);
    ff_wquant<<<2048, 256>>>(w1, NW1 / 4, 0);
    ff_wabs_part<<<512, 256>>>(w2, NW2, 1);
    ff_wgamma_final<<<1, 32>>>(NW2, 1);
    ff_wquant<<<2048, 256>>>(w2, NW2 / 4, 1);

    // Layer-1 quantile (3-level radix select over |h1|)
    ff_init_select<<<1, 256>>>(RANK1);
    ff_hist<<<2048, 256>>>(N1 / 4, 21, 2047);
    ff_scan<<<1, 256>>>(21, 2048, 0, 0);
    ff_hist<<<2048, 256>>>(N1 / 4, 10, 2047);
    ff_scan<<<1, 256>>>(10, 2048, 0, 0);
    ff_hist<<<2048, 256>>>(N1 / 4, 0, 1023);
    ff_scan<<<1, 256>>>(0, 1024, 1, 0);

    // Quantize acts #1 -> int8
    ff_actquant1<<<4096, 256>>>(N1 / 4);

    // GEMM1 (int8 tensor cores) -> exact i16 integers
    ff_gemm_i8<0><<<dim3(MM / 128, HDIM / 128), 256>>>(nullptr);

    // Layer-2 quantile from integer histogram (exact + interpolation)
    ff_h2zero<<<256, 256>>>();
    ff_hist2<<<512, 256>>>(N2 / 8);
    ff_scan2<<<1, 256>>>();
    ff_lut_build<<<256, 256>>>();

    // GELU + quantize acts #2 via LUT
    ff_actquant2<<<8192, 256>>>(N2 / 8);

    // GEMM2 (int8 tensor cores) -> fp32 output
    ff_gemm_i8<1><<<dim3(MM / 128, DDIM / 128), 256>>>(out);
}

// round 6
// speedup vs baseline: 1.7581x; 1.7581x over previous
#include <cuda_runtime.h>
#include <cuda_bf16.h>
#include <cstdint>
#include <cstddef>

#define DEV __device__ __forceinline__

// ---------------- problem dims ----------------
#define DDIM 1024
#define HDIM 4096
#define MM   16384
#define N1  ((long long)MM * DDIM)        // 16,777,216
#define N2  ((long long)MM * HDIM)        // 67,108,864
#define NW1 ((long long)HDIM * DDIM)
#define NW2 ((long long)DDIM * HDIM)
#define RANK1 16693329LL                  // nearest-rank 0.995 quantile over N1

// ---------------- device scratch ----------------
__device__ float          g_h1 [(size_t)N1];     // LN output fp32
__device__ __nv_bfloat16  g_h1q[(size_t)N1];     // bf16 acts layer1 (exact ints)
__device__ short          g_n2 [(size_t)N2];     // GEMM1 integer output (exact)
__device__ __nv_bfloat16  g_a2q[(size_t)N2];     // bf16 acts layer2 (exact ints)
__device__ __nv_bfloat16  g_w1q[(size_t)NW1];    // ternary w1
__device__ __nv_bfloat16  g_w2q[(size_t)NW2];    // ternary w2
__device__ unsigned       g_hist2[65536];        // hist of n (offset +32768)
__device__ unsigned short g_lut[65536];          // n -> quantized gelu (bf16 bits)

__device__ unsigned  g_bins[2048];
__device__ unsigned  g_prefix, g_prefmask;
__device__ long long g_rank;
__device__ float     g_s[2];        // s = 127/amax
__device__ float     g_gamma[2];    // gamma = mean|w| + 1e-5
__device__ float     g_sc1;         // gamma1/s1
__device__ double    g_wpart[2][512];

// ---------------- helpers ----------------
DEV float ff_warp_sum(float v) {
    #pragma unroll
    for (int o = 16; o; o >>= 1) v += __shfl_xor_sync(0xffffffffu, v, o);
    return v;
}
DEV float ff_gelu(float x) {
    return 0.5f * x * (1.0f + erff(x * 0.70710678118654752440f));
}
DEV unsigned ff_pack_bf16(float a, float b) {
    __nv_bfloat162 p = __floats2bfloat162_rn(a, b);
    return *reinterpret_cast<unsigned*>(&p);
}
DEV void ff_cp_async16(void* sdst, const void* gsrc) {
    unsigned d = (unsigned)__cvta_generic_to_shared(sdst);
    asm volatile("cp.async.cg.shared.global [%0], [%1], 16;\n" :: "r"(d), "l"(gsrc));
}

// ---------------- layernorm ----------------
__global__ __launch_bounds__(256) void ff_ln_kernel(
    const float* __restrict__ x, const float* __restrict__ gam,
    const float* __restrict__ bet)
{
    int row = blockIdx.x;
    int tid = threadIdx.x, w = tid >> 5, l = tid & 31;
    const float4* xr = (const float4*)(x + (size_t)row * DDIM);
    float4 v = xr[tid];

    __shared__ float sh[8];
    __shared__ float s_mu, s_inv;

    float s = v.x + v.y + v.z + v.w;
    float ws = ff_warp_sum(s);
    if (l == 0) sh[w] = ws;
    __syncthreads();
    if (w == 0) {
        float a = (l < 8) ? sh[l] : 0.0f;
        a = ff_warp_sum(a);
        if (l == 0) s_mu = a * (1.0f / DDIM);
    }
    __syncthreads();
    float mu = s_mu;

    float dx = v.x - mu, dy = v.y - mu, dz = v.z - mu, dw = v.w - mu;
    float ss = dx*dx + dy*dy + dz*dz + dw*dw;
    float wss = ff_warp_sum(ss);
    __syncthreads();
    if (l == 0) sh[w] = wss;
    __syncthreads();
    if (w == 0) {
        float a = (l < 8) ? sh[l] : 0.0f;
        a = ff_warp_sum(a);
        if (l == 0) s_inv = 1.0f / sqrtf(a * (1.0f / DDIM) + 1e-5f);
    }
    __syncthreads();
    float inv = s_inv;

    float4 g4 = ((const float4*)gam)[tid], b4 = ((const float4*)bet)[tid];
    float4 o;
    o.x = dx * inv * g4.x + b4.x;
    o.y = dy * inv * g4.y + b4.y;
    o.z = dz * inv * g4.z + b4.z;
    o.w = dw * inv * g4.w + b4.w;
    ((float4*)(g_h1 + (size_t)row * DDIM))[tid] = o;
}

// ---------------- weight gamma + ternary quantize (bf16) ----------------
__global__ __launch_bounds__(256) void ff_wabs_part(const float* __restrict__ w,
                                                    long long n, int idx)
{
    long long per = n / gridDim.x;
    long long s0 = (long long)blockIdx.x * per;
    double acc = 0.0;
    for (long long i = s0 + threadIdx.x; i < s0 + per; i += blockDim.x)
        acc += (double)fabsf(w[i]);
    __shared__ double sd[256];
    sd[threadIdx.x] = acc;
    __syncthreads();
    for (int o = 128; o; o >>= 1) {
        if (threadIdx.x < o) sd[threadIdx.x] += sd[threadIdx.x + o];
        __syncthreads();
    }
    if (threadIdx.x == 0) g_wpart[idx][blockIdx.x] = sd[0];
}

__global__ void ff_wgamma_final(long long n, int idx) {
    if (threadIdx.x == 0) {
        double s = 0.0;
        for (int i = 0; i < 512; i++) s += g_wpart[idx][i];
        g_gamma[idx] = (float)(s / (double)n) + 1e-5f;
    }
}

__global__ __launch_bounds__(256) void ff_wquant(const float* __restrict__ w,
                                                 long long n4, int idx)
{
    float g = g_gamma[idx];
    __nv_bfloat16* out = idx ? g_w2q : g_w1q;
    long long stride = (long long)gridDim.x * blockDim.x;
    const float4* p = (const float4*)w;
    for (long long i = (long long)blockIdx.x * blockDim.x + threadIdx.x; i < n4; i += stride) {
        float4 v = p[i];
        float t0 = fminf(fmaxf(rintf(v.x / g), -1.0f), 1.0f);
        float t1 = fminf(fmaxf(rintf(v.y / g), -1.0f), 1.0f);
        float t2 = fminf(fmaxf(rintf(v.z / g), -1.0f), 1.0f);
        float t3 = fminf(fmaxf(rintf(v.w / g), -1.0f), 1.0f);
        uint2 o;
        o.x = ff_pack_bf16(t0, t1);
        o.y = ff_pack_bf16(t2, t3);
        ((uint2*)out)[i] = o;
    }
}

// ---------------- layer-1 radix select over |g_h1| ----------------
__global__ void ff_init_select(long long rank) {
    if (threadIdx.x == 0) { g_rank = rank; g_prefix = 0u; g_prefmask = 0u; }
    for (int i = threadIdx.x; i < 2048; i += blockDim.x) g_bins[i] = 0u;
}

__global__ __launch_bounds__(256) void ff_hist(long long n4, int shift, unsigned binmask) {
    __shared__ unsigned sb[2048];
    for (int i = threadIdx.x; i < 2048; i += blockDim.x) sb[i] = 0u;
    __syncthreads();
    unsigned pref = g_prefix, pmask = g_prefmask;
    const float4* p = (const float4*)(const float*)g_h1;
    long long stride = (long long)gridDim.x * blockDim.x;
    for (long long i = (long long)blockIdx.x * blockDim.x + threadIdx.x; i < n4; i += stride) {
        float4 v = p[i];
        unsigned u;
        u = __float_as_uint(fabsf(v.x)); if ((u & pmask) == pref) atomicAdd(&sb[(u >> shift) & binmask], 1u);
        u = __float_as_uint(fabsf(v.y)); if ((u & pmask) == pref) atomicAdd(&sb[(u >> shift) & binmask], 1u);
        u = __float_as_uint(fabsf(v.z)); if ((u & pmask) == pref) atomicAdd(&sb[(u >> shift) & binmask], 1u);
        u = __float_as_uint(fabsf(v.w)); if ((u & pmask) == pref) atomicAdd(&sb[(u >> shift) & binmask], 1u);
    }
    __syncthreads();
    for (int i = threadIdx.x; i < 2048; i += blockDim.x)
        if (sb[i]) atomicAdd(&g_bins[i], sb[i]);
}

__global__ void ff_scan(int shift, int nbins, int is_final, int sidx) {
    if (threadIdx.x == 0) {
        long long r = g_rank, cum = 0;
        int sel = nbins - 1;
        for (int b = 0; b < nbins; b++) {
            unsigned c = g_bins[b];
            if (cum + (long long)c > r) { sel = b; g_rank = r - cum; break; }
            cum += c;
        }
        unsigned pref = g_prefix | ((unsigned)sel << shift);
        if (is_final) {
            float amax = fmaxf(__uint_as_float(pref), 1e-5f);
            g_s[sidx] = 127.0f / amax;
        } else {
            g_prefix = pref;
            g_prefmask |= ((unsigned)(nbins - 1)) << shift;
        }
    }
    __syncthreads();
    for (int i = threadIdx.x; i < 2048; i += blockDim.x) g_bins[i] = 0u;
}

// ---------------- layer-1 activation quantize -> bf16 ints ----------------
__global__ __launch_bounds__(256) void ff_actquant1(long long n4) {
    float s = g_s[0];
    const float4* in = (const float4*)(const float*)g_h1;
    uint2* out = (uint2*)g_h1q;
    long long stride = (long long)gridDim.x * blockDim.x;
    for (long long i = (long long)blockIdx.x * blockDim.x + threadIdx.x; i < n4; i += stride) {
        float4 v = in[i];
        float q0 = fminf(fmaxf(rintf(v.x * s), -128.0f), 127.0f);
        float q1 = fminf(fmaxf(rintf(v.y * s), -128.0f), 127.0f);
        float q2 = fminf(fmaxf(rintf(v.z * s), -128.0f), 127.0f);
        float q3 = fminf(fmaxf(rintf(v.w * s), -128.0f), 127.0f);
        uint2 o;
        o.x = ff_pack_bf16(q0, q1);
        o.y = ff_pack_bf16(q2, q3);
        out[i] = o;
    }
}

// ---------------- bf16 tensor-core GEMM (proven R2 core) ----------------
// C[M][N] = scale * A[M][K] x B[N][K]^T ; LAYER 0 stores exact i16, LAYER 1 fp32
DEV void ff_load_stage(const __nv_bfloat16* A, const __nv_bfloat16* Bw, int K,
                       int bm, int bn, int kt, unsigned char* sa, int tid)
{
    unsigned char* sb = sa + 8192;
    #pragma unroll
    for (int i = 0; i < 2; i++) {
        int c = tid + i * 256;
        int row = c >> 2, ch = c & 3;
        int sw = ch ^ ((row >> 1) & 3);
        ff_cp_async16(sa + (row * 4 + sw) * 16, A  + (size_t)(bm + row) * K + kt * 32 + ch * 8);
        ff_cp_async16(sb + (row * 4 + sw) * 16, Bw + (size_t)(bn + row) * K + kt * 32 + ch * 8);
    }
    asm volatile("cp.async.commit_group;\n");
}

template<int LAYER>
__global__ __launch_bounds__(256, 2) void ff_gemm(float* __restrict__ Cext)
{
    constexpr int KD = LAYER ? HDIM : DDIM;
    constexpr int ND = LAYER ? DDIM : HDIM;
    constexpr int KT = KD >> 5;
    const __nv_bfloat16* A  = LAYER ? g_a2q : g_h1q;
    const __nv_bfloat16* Bw = LAYER ? g_w2q : g_w1q;

    __shared__ __align__(128) unsigned char smem[3 * 16384];
    const int tid  = threadIdx.x;
    const int lane = tid & 31, warp = tid >> 5;
    const int wm = warp >> 2, wn = warp & 3;     // 2 x 4 warp grid
    const int bm = blockIdx.y * 128, bn = blockIdx.x * 128;   // N on x (L2 reuse!)

    float acc[4][4][4];
    #pragma unroll
    for (int a = 0; a < 4; a++)
        #pragma unroll
        for (int b = 0; b < 4; b++)
            #pragma unroll
            for (int c = 0; c < 4; c++) acc[a][b][c] = 0.0f;

    ff_load_stage(A, Bw, KD, bm, bn, 0, smem + 0 * 16384, tid);
    ff_load_stage(A, Bw, KD, bm, bn, 1, smem + 1 * 16384, tid);

    for (int kt = 0; kt < KT; kt++) {
        if (kt < KT - 1) asm volatile("cp.async.wait_group 1;\n" ::: "memory");
        else             asm volatile("cp.async.wait_group 0;\n" ::: "memory");
        __syncthreads();
        if (kt + 2 < KT)
            ff_load_stage(A, Bw, KD, bm, bn, kt + 2, smem + ((kt + 2) % 3) * 16384, tid);

        unsigned char* sa = smem + (kt % 3) * 16384;
        unsigned char* sb = sa + 8192;

        #pragma unroll
        for (int s = 0; s < 2; s++) {
            unsigned ar[4][4];
            #pragma unroll
            for (int mi = 0; mi < 4; mi++) {
                int row = wm * 64 + mi * 16 + ((lane >> 3) & 1) * 8 + (lane & 7);
                int ch  = (2 * s + (lane >> 4)) ^ ((row >> 1) & 3);
                unsigned addr = (unsigned)__cvta_generic_to_shared(sa + (row * 4 + ch) * 16);
                asm volatile("ldmatrix.sync.aligned.m8n8.x4.shared.b16 {%0,%1,%2,%3}, [%4];\n"
                    : "=r"(ar[mi][0]), "=r"(ar[mi][1]), "=r"(ar[mi][2]), "=r"(ar[mi][3])
                    : "r"(addr));
            }
            unsigned br[4][2];
            #pragma unroll
            for (int nj2 = 0; nj2 < 2; nj2++) {
                int row = wn * 32 + nj2 * 16 + ((lane >> 3) & 1) * 8 + (lane & 7);
                int ch  = (2 * s + (lane >> 4)) ^ ((row >> 1) & 3);
                unsigned addr = (unsigned)__cvta_generic_to_shared(sb + (row * 4 + ch) * 16);
                unsigned q0, q1, q2, q3;
                asm volatile("ldmatrix.sync.aligned.m8n8.x4.shared.b16 {%0,%1,%2,%3}, [%4];\n"
                    : "=r"(q0), "=r"(q1), "=r"(q2), "=r"(q3) : "r"(addr));
                br[2 * nj2][0] = q0;     br[2 * nj2][1] = q2;
                br[2 * nj2 + 1][0] = q1; br[2 * nj2 + 1][1] = q3;
            }
            #pragma unroll
            for (int mi = 0; mi < 4; mi++)
                #pragma unroll
                for (int nj = 0; nj < 4; nj++) {
                    asm volatile(
                        "mma.sync.aligned.m16n8k16.row.col.f32.bf16.bf16.f32 "
                        "{%0,%1,%2,%3},{%4,%5,%6,%7},{%8,%9},{%0,%1,%2,%3};\n"
                        : "+f"(acc[mi][nj][0]), "+f"(acc[mi][nj][1]),
                          "+f"(acc[mi][nj][2]), "+f"(acc[mi][nj][3])
                        : "r"(ar[mi][0]), "r"(ar[mi][1]), "r"(ar[mi][2]), "r"(ar[mi][3]),
                          "r"(br[nj][0]), "r"(br[nj][1]));
                }
        }
    }

    if (LAYER == 0) {
        // exact integers -> i16 (values ~N(0,950), i16 clamp is safety only)
        #pragma unroll
        for (int mi = 0; mi < 4; mi++) {
            int r0 = bm + wm * 64 + mi * 16 + (lane >> 2);
            #pragma unroll
            for (int nj = 0; nj < 4; nj++) {
                int cc = bn + wn * 32 + nj * 8 + (lane & 3) * 2;
                int c0 = min(max((int)acc[mi][nj][0], -32768), 32767);
                int c1 = min(max((int)acc[mi][nj][1], -32768), 32767);
                int c2 = min(max((int)acc[mi][nj][2], -32768), 32767);
                int c3 = min(max((int)acc[mi][nj][3], -32768), 32767);
                *(unsigned*)(g_n2 + (size_t)r0 * ND + cc) =
                    ((unsigned)(unsigned short)(short)c0) | (((unsigned)(unsigned short)(short)c1) << 16);
                *(unsigned*)(g_n2 + (size_t)(r0 + 8) * ND + cc) =
                    ((unsigned)(unsigned short)(short)c2) | (((unsigned)(unsigned short)(short)c3) << 16);
            }
        }
    } else {
        float sc = g_gamma[1] / g_s[1];
        #pragma unroll
        for (int mi = 0; mi < 4; mi++) {
            int r0 = bm + wm * 64 + mi * 16 + (lane >> 2);
            #pragma unroll
            for (int nj = 0; nj < 4; nj++) {
                int cc = bn + wn * 32 + nj * 8 + (lane & 3) * 2;
                float2 p0 = make_float2(acc[mi][nj][0] * sc, acc[mi][nj][1] * sc);
                float2 p1 = make_float2(acc[mi][nj][2] * sc, acc[mi][nj][3] * sc);
                *(float2*)(Cext + (size_t)r0 * ND + cc) = p0;
                *(float2*)(Cext + (size_t)(r0 + 8) * ND + cc) = p1;
            }
        }
    }
}

// ---------------- layer-2 integer histogram ----------------
__global__ void ff_h2zero() {
    g_hist2[blockIdx.x * blockDim.x + threadIdx.x] = 0u;   // 256x256
}

__global__ __launch_bounds__(256) void ff_hist2(long long n8) {
    __shared__ unsigned sb[8192];                           // core range [-4096, 4095]
    for (int i = threadIdx.x; i < 8192; i += blockDim.x) sb[i] = 0u;
    __syncthreads();
    const uint4* p = (const uint4*)g_n2;
    long long stride = (long long)gridDim.x * blockDim.x;
    for (long long i = (long long)blockIdx.x * blockDim.x + threadIdx.x; i < n8; i += stride) {
        uint4 v = p[i];
        unsigned ww[4] = {v.x, v.y, v.z, v.w};
        #pragma unroll
        for (int j = 0; j < 4; j++) {
            int n0 = (int)(short)(ww[j] & 0xffffu);
            int n1 = (int)(short)(ww[j] >> 16);
            int b0 = n0 + 4096, b1 = n1 + 4096;
            if ((unsigned)b0 < 8192u) atomicAdd(&sb[b0], 1u); else atomicAdd(&g_hist2[n0 + 32768], 1u);
            if ((unsigned)b1 < 8192u) atomicAdd(&sb[b1], 1u); else atomicAdd(&g_hist2[n1 + 32768], 1u);
        }
    }
    __syncthreads();
    for (int i = threadIdx.x; i < 8192; i += blockDim.x)
        if (sb[i]) atomicAdd(&g_hist2[i + (32768 - 4096)], sb[i]);
}

// ---------------- layer-2 quantile (interpolated, exact) ----------------
__global__ void ff_scan2() {
    __shared__ long long partial[256];
    int t = threadIdx.x;
    long long c = 0;
    for (int b = t * 256; b < (t + 1) * 256; b++) c += (long long)g_hist2[b];
    partial[t] = c;
    __syncthreads();
    if (t == 0) {
        double idx = 0.995 * (double)(N2 - 1);
        long long k = (long long)idx;
        double f = idx - (double)k;
        long long cum = 0;
        int chunk = 0;
        for (; chunk < 256; chunk++) {
            if (cum + partial[chunk] > k) break;
            cum += partial[chunk];
        }
        long long r = k - cum;
        int nk = 0, nk1 = 0;
        int b = chunk * 256;
        for (;; b++) {
            long long cc = (long long)g_hist2[b];
            if (r < cc) {
                nk = b - 32768;
                if (r + 1 < cc) nk1 = nk;
                else {
                    int b2 = b + 1;
                    while (b2 < 65536 && g_hist2[b2] == 0u) b2++;
                    nk1 = (b2 < 65536) ? (b2 - 32768) : nk;
                }
                break;
            }
            r -= cc;
        }
        float sc1 = g_gamma[0] / g_s[0];
        float v0 = ff_gelu(sc1 * (float)nk);
        float v1 = ff_gelu(sc1 * (float)nk1);
        float amax = fmaxf((float)((1.0 - f) * (double)v0 + f * (double)v1), 1e-5f);
        g_s[1] = 127.0f / amax;
        g_sc1 = sc1;
    }
}

// ---------------- LUT: n -> quantized gelu value as bf16 bits ----------------
__global__ void ff_lut_build() {
    int i = blockIdx.x * blockDim.x + threadIdx.x;   // 65536
    int n = i - 32768;
    float g = ff_gelu(g_sc1 * (float)n);
    float q = fminf(fmaxf(rintf(g * g_s[1]), -128.0f), 127.0f);
    __nv_bfloat16 b = __float2bfloat16(q);           // exact (integer <= 128)
    g_lut[i] = *reinterpret_cast<unsigned short*>(&b);
}

// ---------------- layer-2 quantize via LUT gather -> bf16 ----------------
__global__ __launch_bounds__(256) void ff_actquant2(long long n8) {
    const uint4* in = (const uint4*)g_n2;
    uint4* out = (uint4*)g_a2q;
    const unsigned short* lut = g_lut;
    long long stride = (long long)gridDim.x * blockDim.x;
    for (long long i = (long long)blockIdx.x * blockDim.x + threadIdx.x; i < n8; i += stride) {
        uint4 v = in[i];
        unsigned ww[4] = {v.x, v.y, v.z, v.w};
        unsigned ov[4];
        #pragma unroll
        for (int j = 0; j < 4; j++) {
            unsigned lo = lut[(ww[j] & 0xffffu) ^ 0x8000u];
            unsigned hi = lut[(ww[j] >> 16) ^ 0x8000u];
            ov[j] = lo | (hi << 16);
        }
        out[i] = make_uint4(ov[0], ov[1], ov[2], ov[3]);
    }
}

// ---------------- launch ----------------
extern "C" void kernel_launch(void* const* d_in, const int* in_sizes, int n_in,
                              void* d_out, int out_size)
{
    const float* x    = (const float*)d_in[0];
    const float* ln_g = (const float*)d_in[1];
    const float* ln_b = (const float*)d_in[2];
    const float* w1   = (const float*)d_in[3];
    const float* w2   = (const float*)d_in[4];
    float* out = (float*)d_out;

    // LayerNorm
    ff_ln_kernel<<<MM, 256>>>(x, ln_g, ln_b);

    // Weight ternarization
    ff_wabs_part<<<512, 256>>>(w1, NW1, 0);
    ff_wgamma_final<<<1, 32>>>(NW1, 0);
    ff_wquant<<<2048, 256>>>(w1, NW1 / 4, 0);
    ff_wabs_part<<<512, 256>>>(w2, NW2, 1);
    ff_wgamma_final<<<1, 32>>>(NW2, 1);
    ff_wquant<<<2048, 256>>>(w2, NW2 / 4, 1);

    // Layer-1 quantile (3-level radix select over |h1|)
    ff_init_select<<<1, 256>>>(RANK1);
    ff_hist<<<2048, 256>>>(N1 / 4, 21, 2047);
    ff_scan<<<1, 256>>>(21, 2048, 0, 0);
    ff_hist<<<2048, 256>>>(N1 / 4, 10, 2047);
    ff_scan<<<1, 256>>>(10, 2048, 0, 0);
    ff_hist<<<2048, 256>>>(N1 / 4, 0, 1023);
    ff_scan<<<1, 256>>>(0, 1024, 1, 0);

    // Quantize acts #1 -> bf16 ints
    ff_actquant1<<<4096, 256>>>(N1 / 4);

    // GEMM1 (bf16 tensor cores) -> exact i16 integers
    ff_gemm<0><<<dim3(HDIM / 128, MM / 128), 256>>>(nullptr);

    // Layer-2 quantile from integer histogram (exact + interpolation)
    ff_h2zero<<<256, 256>>>();
    ff_hist2<<<512, 256>>>(N2 / 8);
    ff_scan2<<<1, 256>>>();
    ff_lut_build<<<256, 256>>>();

    // GELU + quantize acts #2 via LUT -> bf16 ints
    ff_actquant2<<<8192, 256>>>(N2 / 8);

    // GEMM2 (bf16 tensor cores) -> fp32 output
    ff_gemm<1><<<dim3(DDIM / 128, MM / 128), 256>>>(out);
}

// round 7
// speedup vs baseline: 1.7922x; 1.0194x over previous
#include <cuda_runtime.h>
#include <cuda_bf16.h>
#include <cstdint>
#include <cstddef>

#define DEV __device__ __forceinline__

// ---------------- problem dims ----------------
#define DDIM 1024
#define HDIM 4096
#define MM   16384
#define N1  ((long long)MM * DDIM)        // 16,777,216
#define N2  ((long long)MM * HDIM)        // 67,108,864
#define NW1 ((long long)HDIM * DDIM)
#define NW2 ((long long)DDIM * HDIM)
#define RANK1 16693329LL                  // nearest-rank 0.995 quantile over N1

// ---------------- device scratch ----------------
__device__ float          g_h1 [(size_t)N1];     // LN output fp32
__device__ __nv_bfloat16  g_h1q[(size_t)N1];     // bf16 acts layer1 (exact ints)
__device__ short          g_n2 [(size_t)N2];     // GEMM1 integer output (exact)
__device__ __nv_bfloat16  g_a2q[(size_t)N2];     // bf16 acts layer2 (exact ints)
__device__ __nv_bfloat16  g_w1q[(size_t)NW1];    // ternary w1
__device__ __nv_bfloat16  g_w2q[(size_t)NW2];    // ternary w2
__device__ unsigned       g_hist2[65536];        // hist of n (offset +32768); re-zeroed each run
__device__ unsigned short g_lut[65536];          // n -> quantized gelu (bf16 bits)

__device__ unsigned  g_bins[2048];               // radix-select bins (self-rezeroing)
__device__ unsigned  g_prefix, g_prefmask;
__device__ long long g_rank;
__device__ float     g_s[2];        // s = 127/amax
__device__ float     g_gamma[2];    // gamma = mean|w| + 1e-5
__device__ float     g_sc1;         // gamma1/s1
__device__ double    g_wpart[2][512];
__device__ unsigned  g_ctr[4];      // last-block counters (self-resetting)

// ---------------- helpers ----------------
DEV float ff_warp_sum(float v) {
    #pragma unroll
    for (int o = 16; o; o >>= 1) v += __shfl_xor_sync(0xffffffffu, v, o);
    return v;
}
DEV float ff_gelu(float x) {
    return 0.5f * x * (1.0f + erff(x * 0.70710678118654752440f));
}
DEV unsigned ff_pack_bf16(float a, float b) {
    __nv_bfloat162 p = __floats2bfloat162_rn(a, b);
    return *reinterpret_cast<unsigned*>(&p);
}
DEV void ff_cp_async16(void* sdst, const void* gsrc) {
    unsigned d = (unsigned)__cvta_generic_to_shared(sdst);
    asm volatile("cp.async.cg.shared.global [%0], [%1], 16;\n" :: "r"(d), "l"(gsrc));
}
// returns true (uniformly per block) if this is the last block to finish
DEV bool ff_last_block(int slot) {
    __shared__ bool isLast;
    if (threadIdx.x == 0) {
        __threadfence();
        unsigned v = atomicAdd(&g_ctr[slot], 1u);
        isLast = (v == gridDim.x - 1);
    }
    __syncthreads();
    return isLast;
}

// ---------------- layernorm ----------------
__global__ __launch_bounds__(256) void ff_ln_kernel(
    const float* __restrict__ x, const float* __restrict__ gam,
    const float* __restrict__ bet)
{
    int row = blockIdx.x;
    int tid = threadIdx.x, w = tid >> 5, l = tid & 31;
    const float4* xr = (const float4*)(x + (size_t)row * DDIM);
    float4 v = xr[tid];

    __shared__ float sh[8];
    __shared__ float s_mu, s_inv;

    float s = v.x + v.y + v.z + v.w;
    float ws = ff_warp_sum(s);
    if (l == 0) sh[w] = ws;
    __syncthreads();
    if (w == 0) {
        float a = (l < 8) ? sh[l] : 0.0f;
        a = ff_warp_sum(a);
        if (l == 0) s_mu = a * (1.0f / DDIM);
    }
    __syncthreads();
    float mu = s_mu;

    float dx = v.x - mu, dy = v.y - mu, dz = v.z - mu, dw = v.w - mu;
    float ss = dx*dx + dy*dy + dz*dz + dw*dw;
    float wss = ff_warp_sum(ss);
    __syncthreads();
    if (l == 0) sh[w] = wss;
    __syncthreads();
    if (w == 0) {
        float a = (l < 8) ? sh[l] : 0.0f;
        a = ff_warp_sum(a);
        if (l == 0) s_inv = 1.0f / sqrtf(a * (1.0f / DDIM) + 1e-5f);
    }
    __syncthreads();
    float inv = s_inv;

    float4 g4 = ((const float4*)gam)[tid], b4 = ((const float4*)bet)[tid];
    float4 o;
    o.x = dx * inv * g4.x + b4.x;
    o.y = dy * inv * g4.y + b4.y;
    o.z = dz * inv * g4.z + b4.z;
    o.w = dw * inv * g4.w + b4.w;
    ((float4*)(g_h1 + (size_t)row * DDIM))[tid] = o;
}

// ---------------- weight |w| mean + gamma (fused last-block) ----------------
__global__ __launch_bounds__(256) void ff_wabs(const float* __restrict__ w,
                                               long long n, int idx)
{
    long long per = n / gridDim.x;
    long long s0 = (long long)blockIdx.x * per;
    double acc = 0.0;
    for (long long i = s0 + threadIdx.x; i < s0 + per; i += blockDim.x)
        acc += (double)fabsf(w[i]);
    __shared__ double sd[256];
    sd[threadIdx.x] = acc;
    __syncthreads();
    for (int o = 128; o; o >>= 1) {
        if (threadIdx.x < o) sd[threadIdx.x] += sd[threadIdx.x + o];
        __syncthreads();
    }
    if (threadIdx.x == 0) g_wpart[idx][blockIdx.x] = sd[0];

    if (ff_last_block(idx)) {
        if (threadIdx.x == 0) {
            double t = 0.0;
            for (int i = 0; i < 512; i++) t += g_wpart[idx][i];
            g_gamma[idx] = (float)(t / (double)n) + 1e-5f;
            g_ctr[idx] = 0u;
        }
    }
}

// ---------------- ternary weight quantize (bf16) ----------------
__global__ __launch_bounds__(256) void ff_wquant(const float* __restrict__ w,
                                                 long long n4, int idx)
{
    float g = g_gamma[idx];
    __nv_bfloat16* out = idx ? g_w2q : g_w1q;
    long long stride = (long long)gridDim.x * blockDim.x;
    const float4* p = (const float4*)w;
    for (long long i = (long long)blockIdx.x * blockDim.x + threadIdx.x; i < n4; i += stride) {
        float4 v = p[i];
        float t0 = fminf(fmaxf(rintf(v.x / g), -1.0f), 1.0f);
        float t1 = fminf(fmaxf(rintf(v.y / g), -1.0f), 1.0f);
        float t2 = fminf(fmaxf(rintf(v.z / g), -1.0f), 1.0f);
        float t3 = fminf(fmaxf(rintf(v.w / g), -1.0f), 1.0f);
        uint2 o;
        o.x = ff_pack_bf16(t0, t1);
        o.y = ff_pack_bf16(t2, t3);
        ((uint2*)out)[i] = o;
    }
}

// ---------------- layer-1 radix select: hist + fused scan ----------------
__global__ __launch_bounds__(256) void ff_hist_scan(long long n4, int shift,
                                                    unsigned binmask, int is_first,
                                                    int is_final)
{
    __shared__ unsigned sb[2048];
    for (int i = threadIdx.x; i < 2048; i += blockDim.x) sb[i] = 0u;
    __syncthreads();
    unsigned pref  = is_first ? 0u : g_prefix;
    unsigned pmask = is_first ? 0u : g_prefmask;
    const float4* p = (const float4*)(const float*)g_h1;
    long long stride = (long long)gridDim.x * blockDim.x;
    for (long long i = (long long)blockIdx.x * blockDim.x + threadIdx.x; i < n4; i += stride) {
        float4 v = p[i];
        unsigned u;
        u = __float_as_uint(fabsf(v.x)); if ((u & pmask) == pref) atomicAdd(&sb[(u >> shift) & binmask], 1u);
        u = __float_as_uint(fabsf(v.y)); if ((u & pmask) == pref) atomicAdd(&sb[(u >> shift) & binmask], 1u);
        u = __float_as_uint(fabsf(v.z)); if ((u & pmask) == pref) atomicAdd(&sb[(u >> shift) & binmask], 1u);
        u = __float_as_uint(fabsf(v.w)); if ((u & pmask) == pref) atomicAdd(&sb[(u >> shift) & binmask], 1u);
    }
    __syncthreads();
    for (int i = threadIdx.x; i < 2048; i += blockDim.x)
        if (sb[i]) atomicAdd(&g_bins[i], sb[i]);

    if (ff_last_block(2)) {
        if (threadIdx.x == 0) {
            int nbins = (int)binmask + 1;
            long long r = is_first ? RANK1 : g_rank;
            long long cum = 0;
            int sel = nbins - 1;
            for (int b = 0; b < nbins; b++) {
                unsigned c = g_bins[b];
                if (cum + (long long)c > r) { sel = b; r = r - cum; break; }
                cum += c;
            }
            unsigned np = (is_first ? 0u : g_prefix) | ((unsigned)sel << shift);
            if (is_final) {
                float amax = fmaxf(__uint_as_float(np), 1e-5f);
                g_s[0] = 127.0f / amax;
            } else {
                g_prefix   = np;
                g_prefmask = (is_first ? 0u : g_prefmask) | (binmask << shift);
                g_rank     = r;
            }
            g_ctr[2] = 0u;
        }
        __syncthreads();
        for (int i = threadIdx.x; i < 2048; i += blockDim.x) g_bins[i] = 0u;
    }
}

// ---------------- layer-1 activation quantize -> bf16 ints ----------------
__global__ __launch_bounds__(256) void ff_actquant1(long long n4) {
    float s = g_s[0];
    const float4* in = (const float4*)(const float*)g_h1;
    uint2* out = (uint2*)g_h1q;
    long long stride = (long long)gridDim.x * blockDim.x;
    for (long long i = (long long)blockIdx.x * blockDim.x + threadIdx.x; i < n4; i += stride) {
        float4 v = in[i];
        float q0 = fminf(fmaxf(rintf(v.x * s), -128.0f), 127.0f);
        float q1 = fminf(fmaxf(rintf(v.y * s), -128.0f), 127.0f);
        float q2 = fminf(fmaxf(rintf(v.z * s), -128.0f), 127.0f);
        float q3 = fminf(fmaxf(rintf(v.w * s), -128.0f), 127.0f);
        uint2 o;
        o.x = ff_pack_bf16(q0, q1);
        o.y = ff_pack_bf16(q2, q3);
        out[i] = o;
    }
}

// ---------------- bf16 tensor-core GEMM, 4-stage cp.async pipeline ----------------
// C[M][N] = scale * A[M][K] x B[N][K]^T ; LAYER 0 stores exact i16, LAYER 1 fp32
#define GSTG 16384
#define GSMEM (4 * GSTG)

DEV void ff_load_stage(const __nv_bfloat16* A, const __nv_bfloat16* Bw, int K,
                       int bm, int bn, int kt, unsigned char* sa, int tid)
{
    unsigned char* sb = sa + 8192;
    #pragma unroll
    for (int i = 0; i < 2; i++) {
        int c = tid + i * 256;
        int row = c >> 2, ch = c & 3;
        int sw = ch ^ ((row >> 1) & 3);
        ff_cp_async16(sa + (row * 4 + sw) * 16, A  + (size_t)(bm + row) * K + kt * 32 + ch * 8);
        ff_cp_async16(sb + (row * 4 + sw) * 16, Bw + (size_t)(bn + row) * K + kt * 32 + ch * 8);
    }
    asm volatile("cp.async.commit_group;\n");
}

template<int LAYER>
__global__ __launch_bounds__(256, 2) void ff_gemm(float* __restrict__ Cext)
{
    constexpr int KD = LAYER ? HDIM : DDIM;
    constexpr int ND = LAYER ? DDIM : HDIM;
    constexpr int KT = KD >> 5;
    const __nv_bfloat16* A  = LAYER ? g_a2q : g_h1q;
    const __nv_bfloat16* Bw = LAYER ? g_w2q : g_w1q;

    extern __shared__ __align__(128) unsigned char smem[];
    const int tid  = threadIdx.x;
    const int lane = tid & 31, warp = tid >> 5;
    const int wm = warp >> 2, wn = warp & 3;     // 2 x 4 warp grid
    const int bm = blockIdx.y * 128, bn = blockIdx.x * 128;   // N on x (L2 reuse)

    float acc[4][4][4];
    #pragma unroll
    for (int a = 0; a < 4; a++)
        #pragma unroll
        for (int b = 0; b < 4; b++)
            #pragma unroll
            for (int c = 0; c < 4; c++) acc[a][b][c] = 0.0f;

    ff_load_stage(A, Bw, KD, bm, bn, 0, smem + 0 * GSTG, tid);
    ff_load_stage(A, Bw, KD, bm, bn, 1, smem + 1 * GSTG, tid);
    ff_load_stage(A, Bw, KD, bm, bn, 2, smem + 2 * GSTG, tid);

    for (int kt = 0; kt < KT; kt++) {
        if (kt < KT - 2)      asm volatile("cp.async.wait_group 2;\n" ::: "memory");
        else if (kt == KT - 2) asm volatile("cp.async.wait_group 1;\n" ::: "memory");
        else                  asm volatile("cp.async.wait_group 0;\n" ::: "memory");
        __syncthreads();
        if (kt + 3 < KT)
            ff_load_stage(A, Bw, KD, bm, bn, kt + 3, smem + ((kt + 3) & 3) * GSTG, tid);

        unsigned char* sa = smem + (kt & 3) * GSTG;
        unsigned char* sb = sa + 8192;

        #pragma unroll
        for (int s = 0; s < 2; s++) {
            unsigned ar[4][4];
            #pragma unroll
            for (int mi = 0; mi < 4; mi++) {
                int row = wm * 64 + mi * 16 + ((lane >> 3) & 1) * 8 + (lane & 7);
                int ch  = (2 * s + (lane >> 4)) ^ ((row >> 1) & 3);
                unsigned addr = (unsigned)__cvta_generic_to_shared(sa + (row * 4 + ch) * 16);
                asm volatile("ldmatrix.sync.aligned.m8n8.x4.shared.b16 {%0,%1,%2,%3}, [%4];\n"
                    : "=r"(ar[mi][0]), "=r"(ar[mi][1]), "=r"(ar[mi][2]), "=r"(ar[mi][3])
                    : "r"(addr));
            }
            unsigned br[4][2];
            #pragma unroll
            for (int nj2 = 0; nj2 < 2; nj2++) {
                int row = wn * 32 + nj2 * 16 + ((lane >> 3) & 1) * 8 + (lane & 7);
                int ch  = (2 * s + (lane >> 4)) ^ ((row >> 1) & 3);
                unsigned addr = (unsigned)__cvta_generic_to_shared(sb + (row * 4 + ch) * 16);
                unsigned q0, q1, q2, q3;
                asm volatile("ldmatrix.sync.aligned.m8n8.x4.shared.b16 {%0,%1,%2,%3}, [%4];\n"
                    : "=r"(q0), "=r"(q1), "=r"(q2), "=r"(q3) : "r"(addr));
                br[2 * nj2][0] = q0;     br[2 * nj2][1] = q2;
                br[2 * nj2 + 1][0] = q1; br[2 * nj2 + 1][1] = q3;
            }
            #pragma unroll
            for (int mi = 0; mi < 4; mi++)
                #pragma unroll
                for (int nj = 0; nj < 4; nj++) {
                    asm volatile(
                        "mma.sync.aligned.m16n8k16.row.col.f32.bf16.bf16.f32 "
                        "{%0,%1,%2,%3},{%4,%5,%6,%7},{%8,%9},{%0,%1,%2,%3};\n"
                        : "+f"(acc[mi][nj][0]), "+f"(acc[mi][nj][1]),
                          "+f"(acc[mi][nj][2]), "+f"(acc[mi][nj][3])
                        : "r"(ar[mi][0]), "r"(ar[mi][1]), "r"(ar[mi][2]), "r"(ar[mi][3]),
                          "r"(br[nj][0]), "r"(br[nj][1]));
                }
        }
    }

    if (LAYER == 0) {
        // exact integers -> i16
        #pragma unroll
        for (int mi = 0; mi < 4; mi++) {
            int r0 = bm + wm * 64 + mi * 16 + (lane >> 2);
            #pragma unroll
            for (int nj = 0; nj < 4; nj++) {
                int cc = bn + wn * 32 + nj * 8 + (lane & 3) * 2;
                int c0 = min(max((int)acc[mi][nj][0], -32768), 32767);
                int c1 = min(max((int)acc[mi][nj][1], -32768), 32767);
                int c2 = min(max((int)acc[mi][nj][2], -32768), 32767);
                int c3 = min(max((int)acc[mi][nj][3], -32768), 32767);
                *(unsigned*)(g_n2 + (size_t)r0 * ND + cc) =
                    ((unsigned)(unsigned short)(short)c0) | (((unsigned)(unsigned short)(short)c1) << 16);
                *(unsigned*)(g_n2 + (size_t)(r0 + 8) * ND + cc) =
                    ((unsigned)(unsigned short)(short)c2) | (((unsigned)(unsigned short)(short)c3) << 16);
            }
        }
    } else {
        float sc = g_gamma[1] / g_s[1];
        #pragma unroll
        for (int mi = 0; mi < 4; mi++) {
            int r0 = bm + wm * 64 + mi * 16 + (lane >> 2);
            #pragma unroll
            for (int nj = 0; nj < 4; nj++) {
                int cc = bn + wn * 32 + nj * 8 + (lane & 3) * 2;
                float2 p0 = make_float2(acc[mi][nj][0] * sc, acc[mi][nj][1] * sc);
                float2 p1 = make_float2(acc[mi][nj][2] * sc, acc[mi][nj][3] * sc);
                *(float2*)(Cext + (size_t)r0 * ND + cc) = p0;
                *(float2*)(Cext + (size_t)(r0 + 8) * ND + cc) = p1;
            }
        }
    }
}

// ---------------- layer-2 integer histogram + fused quantile scan ----------------
__global__ __launch_bounds__(256) void ff_hist2_scan(long long n8) {
    __shared__ unsigned sb[8192];                           // core range [-4096, 4095]
    for (int i = threadIdx.x; i < 8192; i += blockDim.x) sb[i] = 0u;
    __syncthreads();
    const uint4* p = (const uint4*)g_n2;
    long long stride = (long long)gridDim.x * blockDim.x;
    long long base = (long long)blockIdx.x * blockDim.x + threadIdx.x;
    for (long long i = base; i < n8; i += 2 * stride) {
        uint4 v0 = p[i];
        bool has2 = (i + stride) < n8;
        uint4 v1 = has2 ? p[i + stride] : make_uint4(0, 0, 0, 0);
        unsigned ww[8] = {v0.x, v0.y, v0.z, v0.w, v1.x, v1.y, v1.z, v1.w};
        int cnt = has2 ? 8 : 4;
        #pragma unroll
        for (int j = 0; j < 8; j++) {
            if (j >= cnt) break;
            int n0 = (int)(short)(ww[j] & 0xffffu);
            int n1 = (int)(short)(ww[j] >> 16);
            int b0 = n0 + 4096, b1 = n1 + 4096;
            if ((unsigned)b0 < 8192u) atomicAdd(&sb[b0], 1u); else atomicAdd(&g_hist2[n0 + 32768], 1u);
            if ((unsigned)b1 < 8192u) atomicAdd(&sb[b1], 1u); else atomicAdd(&g_hist2[n1 + 32768], 1u);
        }
    }
    __syncthreads();
    for (int i = threadIdx.x; i < 8192; i += blockDim.x)
        if (sb[i]) atomicAdd(&g_hist2[i + (32768 - 4096)], sb[i]);

    if (ff_last_block(3)) {
        __shared__ long long partial[256];
        int t = threadIdx.x;
        long long c = 0;
        for (int b = t * 256; b < (t + 1) * 256; b++) c += (long long)g_hist2[b];
        partial[t] = c;
        __syncthreads();
        if (t == 0) {
            double idx = 0.995 * (double)(N2 - 1);
            long long k = (long long)idx;
            double f = idx - (double)k;
            long long cum = 0;
            int chunk = 0;
            for (; chunk < 256; chunk++) {
                if (cum + partial[chunk] > k) break;
                cum += partial[chunk];
            }
            long long r = k - cum;
            int nk = 0, nk1 = 0;
            int b = chunk * 256;
            for (;; b++) {
                long long cc = (long long)g_hist2[b];
                if (r < cc) {
                    nk = b - 32768;
                    if (r + 1 < cc) nk1 = nk;
                    else {
                        int b2 = b + 1;
                        while (b2 < 65536 && g_hist2[b2] == 0u) b2++;
                        nk1 = (b2 < 65536) ? (b2 - 32768) : nk;
                    }
                    break;
                }
                r -= cc;
            }
            float sc1 = g_gamma[0] / g_s[0];
            float v0 = ff_gelu(sc1 * (float)nk);
            float v1 = ff_gelu(sc1 * (float)nk1);
            float amax = fmaxf((float)((1.0 - f) * (double)v0 + f * (double)v1), 1e-5f);
            g_s[1] = 127.0f / amax;
            g_sc1 = sc1;
            g_ctr[3] = 0u;
        }
    }
}

// ---------------- LUT build (+ re-zero hist2 for next replay) ----------------
__global__ void ff_lut_build() {
    int i = blockIdx.x * blockDim.x + threadIdx.x;   // 65536
    int n = i - 32768;
    float g = ff_gelu(g_sc1 * (float)n);
    float q = fminf(fmaxf(rintf(g * g_s[1]), -128.0f), 127.0f);
    __nv_bfloat16 b = __float2bfloat16(q);           // exact (integer <= 128)
    g_lut[i] = *reinterpret_cast<unsigned short*>(&b);
    g_hist2[i] = 0u;                                  // reset for next graph replay
}

// ---------------- layer-2 quantize via LUT gather -> bf16 ----------------
__global__ __launch_bounds__(256) void ff_actquant2(long long n8) {
    const uint4* in = (const uint4*)g_n2;
    uint4* out = (uint4*)g_a2q;
    const unsigned short* lut = g_lut;
    long long stride = (long long)gridDim.x * blockDim.x;
    long long base = (long long)blockIdx.x * blockDim.x + threadIdx.x;
    for (long long i = base; i < n8; i += 2 * stride) {
        uint4 v0 = in[i];
        unsigned o0[4];
        #pragma unroll
        for (int j = 0; j < 4; j++) {
            unsigned wj = (&v0.x)[j];
            unsigned lo = lut[(wj & 0xffffu) ^ 0x8000u];
            unsigned hi = lut[(wj >> 16) ^ 0x8000u];
            o0[j] = lo | (hi << 16);
        }
        out[i] = make_uint4(o0[0], o0[1], o0[2], o0[3]);
        if (i + stride < n8) {
            uint4 v1 = in[i + stride];
            unsigned o1[4];
            #pragma unroll
            for (int j = 0; j < 4; j++) {
                unsigned wj = (&v1.x)[j];
                unsigned lo = lut[(wj & 0xffffu) ^ 0x8000u];
                unsigned hi = lut[(wj >> 16) ^ 0x8000u];
                o1[j] = lo | (hi << 16);
            }
            out[i + stride] = make_uint4(o1[0], o1[1], o1[2], o1[3]);
        }
    }
}

// ---------------- launch ----------------
extern "C" void kernel_launch(void* const* d_in, const int* in_sizes, int n_in,
                              void* d_out, int out_size)
{
    const float* x    = (const float*)d_in[0];
    const float* ln_g = (const float*)d_in[1];
    const float* ln_b = (const float*)d_in[2];
    const float* w1   = (const float*)d_in[3];
    const float* w2   = (const float*)d_in[4];
    float* out = (float*)d_out;

    cudaFuncSetAttribute(ff_gemm<0>, cudaFuncAttributeMaxDynamicSharedMemorySize, GSMEM);
    cudaFuncSetAttribute(ff_gemm<1>, cudaFuncAttributeMaxDynamicSharedMemorySize, GSMEM);

    // LayerNorm
    ff_ln_kernel<<<MM, 256>>>(x, ln_g, ln_b);

    // Weight ternarization (gamma fused via last-block)
    ff_wabs<<<512, 256>>>(w1, NW1, 0);
    ff_wquant<<<2048, 256>>>(w1, NW1 / 4, 0);
    ff_wabs<<<512, 256>>>(w2, NW2, 1);
    ff_wquant<<<2048, 256>>>(w2, NW2 / 4, 1);

    // Layer-1 quantile: 3-level radix select, scan fused into last block
    ff_hist_scan<<<2048, 256>>>(N1 / 4, 21, 2047u, 1, 0);
    ff_hist_scan<<<2048, 256>>>(N1 / 4, 10, 2047u, 0, 0);
    ff_hist_scan<<<2048, 256>>>(N1 / 4, 0, 1023u, 0, 1);

    // Quantize acts #1 -> bf16 ints
    ff_actquant1<<<4096, 256>>>(N1 / 4);

    // GEMM1 (bf16 tensor cores, 4-stage) -> exact i16 integers
    ff_gemm<0><<<dim3(HDIM / 128, MM / 128), 256, GSMEM>>>(nullptr);

    // Layer-2 quantile: integer histogram + fused scan
    ff_hist2_scan<<<512, 256>>>(N2 / 8);
    ff_lut_build<<<256, 256>>>();

    // GELU + quantize acts #2 via LUT -> bf16 ints
    ff_actquant2<<<4096, 256>>>(N2 / 8);

    // GEMM2 (bf16 tensor cores, 4-stage) -> fp32 output
    ff_gemm<1><<<dim3(DDIM / 128, MM / 128), 256, GSMEM>>>(out);
}

// round 8
// speedup vs baseline: 1.8553x; 1.0352x over previous
#include <cuda_runtime.h>
#include <cuda_bf16.h>
#include <cstdint>
#include <cstddef>

#define DEV __device__ __forceinline__

// ---------------- problem dims ----------------
#define DDIM 1024
#define HDIM 4096
#define MM   16384
#define N1  ((long long)MM * DDIM)        // 16,777,216
#define N2  ((long long)MM * HDIM)        // 67,108,864
#define NW1 ((long long)HDIM * DDIM)      // 4,194,304
#define NW2 ((long long)DDIM * HDIM)      // 4,194,304
#define RANK1 16693329LL                  // nearest-rank 0.995 quantile over N1

// ---------------- device scratch ----------------
__device__ float          g_h1 [(size_t)N1];     // LN output fp32
__device__ __nv_bfloat16  g_h1q[(size_t)N1];     // bf16 acts layer1 (exact ints)
__device__ short          g_n2 [(size_t)N2];     // GEMM1 integer output (exact)
__device__ __nv_bfloat16  g_a2q[(size_t)N2];     // bf16 acts layer2 (exact ints)
__device__ __nv_bfloat16  g_w1q[(size_t)NW1];    // ternary w1
__device__ __nv_bfloat16  g_w2q[(size_t)NW2];    // ternary w2
__device__ unsigned       g_hist2[65536];        // hist of n (offset +32768); re-zeroed each run
__device__ unsigned short g_lut[65536];          // n -> quantized gelu (bf16 bits)

__device__ unsigned  g_bins[2048];               // radix-select bins (self-rezeroing)
__device__ unsigned  g_prefix, g_prefmask;
__device__ long long g_rank;
__device__ float     g_s[2];        // s = 127/amax
__device__ float     g_gamma[2];    // gamma = mean|w| + 1e-5
__device__ float     g_sc1;         // gamma1/s1
__device__ double    g_wpart[2][1024];
__device__ unsigned  g_ctr[4];      // last-block counters (self-resetting)

// ---------------- helpers ----------------
DEV float ff_warp_sum(float v) {
    #pragma unroll
    for (int o = 16; o; o >>= 1) v += __shfl_xor_sync(0xffffffffu, v, o);
    return v;
}
DEV float ff_gelu(float x) {
    return 0.5f * x * (1.0f + erff(x * 0.70710678118654752440f));
}
DEV unsigned ff_pack_bf16(float a, float b) {
    __nv_bfloat162 p = __floats2bfloat162_rn(a, b);
    return *reinterpret_cast<unsigned*>(&p);
}
DEV void ff_cp_async16(void* sdst, const void* gsrc) {
    unsigned d = (unsigned)__cvta_generic_to_shared(sdst);
    asm volatile("cp.async.cg.shared.global [%0], [%1], 16;\n" :: "r"(d), "l"(gsrc));
}
// true (uniform per block) iff this is the last of `total` blocks to arrive at slot
DEV bool ff_last_block_n(int slot, unsigned total) {
    __shared__ bool isLast;
    if (threadIdx.x == 0) {
        __threadfence();
        unsigned v = atomicAdd(&g_ctr[slot], 1u);
        isLast = (v == total - 1);
    }
    __syncthreads();
    return isLast;
}

// ---------------- layernorm with fused radix-select level-0 histogram ----------------
__global__ __launch_bounds__(256) void ff_ln_kernel(
    const float* __restrict__ x, const float* __restrict__ gam,
    const float* __restrict__ bet)
{
    int row = blockIdx.x;
    int tid = threadIdx.x, w = tid >> 5, l = tid & 31;

    __shared__ unsigned sb[2048];
    for (int i = tid; i < 2048; i += 256) sb[i] = 0u;

    const float4* xr = (const float4*)(x + (size_t)row * DDIM);
    float4 v = xr[tid];

    __shared__ float sh[8];
    __shared__ float s_mu, s_inv;

    float s = v.x + v.y + v.z + v.w;
    float ws = ff_warp_sum(s);
    if (l == 0) sh[w] = ws;
    __syncthreads();
    if (w == 0) {
        float a = (l < 8) ? sh[l] : 0.0f;
        a = ff_warp_sum(a);
        if (l == 0) s_mu = a * (1.0f / DDIM);
    }
    __syncthreads();
    float mu = s_mu;

    float dx = v.x - mu, dy = v.y - mu, dz = v.z - mu, dw = v.w - mu;
    float ss = dx*dx + dy*dy + dz*dz + dw*dw;
    float wss = ff_warp_sum(ss);
    __syncthreads();
    if (l == 0) sh[w] = wss;
    __syncthreads();
    if (w == 0) {
        float a = (l < 8) ? sh[l] : 0.0f;
        a = ff_warp_sum(a);
        if (l == 0) s_inv = 1.0f / sqrtf(a * (1.0f / DDIM) + 1e-5f);
    }
    __syncthreads();
    float inv = s_inv;

    float4 g4 = ((const float4*)gam)[tid], b4 = ((const float4*)bet)[tid];
    float4 o;
    o.x = dx * inv * g4.x + b4.x;
    o.y = dy * inv * g4.y + b4.y;
    o.z = dz * inv * g4.z + b4.z;
    o.w = dw * inv * g4.w + b4.w;
    ((float4*)(g_h1 + (size_t)row * DDIM))[tid] = o;

    // fused level-0 histogram of |h| bits (shift 21, 2048 bins)
    atomicAdd(&sb[__float_as_uint(fabsf(o.x)) >> 21], 1u);
    atomicAdd(&sb[__float_as_uint(fabsf(o.y)) >> 21], 1u);
    atomicAdd(&sb[__float_as_uint(fabsf(o.z)) >> 21], 1u);
    atomicAdd(&sb[__float_as_uint(fabsf(o.w)) >> 21], 1u);
    __syncthreads();
    for (int i = tid; i < 2048; i += 256)
        if (sb[i]) atomicAdd(&g_bins[i], sb[i]);
}

// ---------------- level-0 scan (tiny) ----------------
__global__ void ff_scan0() {
    if (threadIdx.x == 0) {
        long long r = RANK1, cum = 0;
        int sel = 2047;
        for (int b = 0; b < 2048; b++) {
            unsigned c = g_bins[b];
            if (cum + (long long)c > r) { sel = b; r = r - cum; break; }
            cum += c;
        }
        g_prefix   = (unsigned)sel << 21;
        g_prefmask = 2047u << 21;
        g_rank     = r;
    }
    __syncthreads();
    for (int i = threadIdx.x; i < 2048; i += blockDim.x) g_bins[i] = 0u;
}

// ---------------- both weights: mean|w| (float partials, fused gamma) ----------------
__global__ __launch_bounds__(256) void ff_wabs2(const float* __restrict__ w1,
                                                const float* __restrict__ w2)
{
    int half = blockIdx.x >> 10;           // grid 2048: 0..1023 -> w1, 1024..2047 -> w2
    int blk  = blockIdx.x & 1023;
    const float4* p = (const float4*)(half ? w2 : w1) + (size_t)blk * 1024;

    float acc = 0.0f;
    #pragma unroll
    for (int i = 0; i < 4; i++) {
        float4 v = p[threadIdx.x + i * 256];
        acc += fabsf(v.x) + fabsf(v.y) + fabsf(v.z) + fabsf(v.w);
    }
    float ws = ff_warp_sum(acc);
    __shared__ float sw[8];
    int wid = threadIdx.x >> 5, l = threadIdx.x & 31;
    if (l == 0) sw[wid] = ws;
    __syncthreads();
    if (threadIdx.x == 0) {
        double b = 0.0;
        for (int i = 0; i < 8; i++) b += (double)sw[i];
        g_wpart[half][blk] = b;
    }

    if (ff_last_block_n(half, 1024)) {
        if (threadIdx.x == 0) {
            double t = 0.0;
            for (int i = 0; i < 1024; i++) t += g_wpart[half][i];
            g_gamma[half] = (float)(t / (double)NW1) + 1e-5f;
            g_ctr[half] = 0u;
        }
    }
}

// ---------------- both weights: ternary quantize (bf16) ----------------
__global__ __launch_bounds__(256) void ff_wquant2(const float* __restrict__ w1,
                                                  const float* __restrict__ w2)
{
    int half = blockIdx.x >> 11;           // grid 4096: halves
    int blk  = blockIdx.x & 2047;
    float g = g_gamma[half];
    const float4* p = (const float4*)(half ? w2 : w1);
    __nv_bfloat16* out = half ? g_w2q : g_w1q;
    long long n4 = NW1 / 4;
    long long stride = 2048LL * 256;
    for (long long i = (long long)blk * 256 + threadIdx.x; i < n4; i += stride) {
        float4 v = p[i];
        float t0 = fminf(fmaxf(rintf(v.x / g), -1.0f), 1.0f);
        float t1 = fminf(fmaxf(rintf(v.y / g), -1.0f), 1.0f);
        float t2 = fminf(fmaxf(rintf(v.z / g), -1.0f), 1.0f);
        float t3 = fminf(fmaxf(rintf(v.w / g), -1.0f), 1.0f);
        uint2 o;
        o.x = ff_pack_bf16(t0, t1);
        o.y = ff_pack_bf16(t2, t3);
        ((uint2*)out)[i] = o;
    }
}

// ---------------- radix-select levels 1,2: hist + fused scan ----------------
__global__ __launch_bounds__(256) void ff_hist_scan(long long n4, int shift,
                                                    unsigned binmask, int is_final)
{
    __shared__ unsigned sb[2048];
    for (int i = threadIdx.x; i < 2048; i += blockDim.x) sb[i] = 0u;
    __syncthreads();
    unsigned pref = g_prefix, pmask = g_prefmask;
    const float4* p = (const float4*)(const float*)g_h1;
    long long stride = (long long)gridDim.x * blockDim.x;
    for (long long i = (long long)blockIdx.x * blockDim.x + threadIdx.x; i < n4; i += stride) {
        float4 v = p[i];
        unsigned u;
        u = __float_as_uint(fabsf(v.x)); if ((u & pmask) == pref) atomicAdd(&sb[(u >> shift) & binmask], 1u);
        u = __float_as_uint(fabsf(v.y)); if ((u & pmask) == pref) atomicAdd(&sb[(u >> shift) & binmask], 1u);
        u = __float_as_uint(fabsf(v.z)); if ((u & pmask) == pref) atomicAdd(&sb[(u >> shift) & binmask], 1u);
        u = __float_as_uint(fabsf(v.w)); if ((u & pmask) == pref) atomicAdd(&sb[(u >> shift) & binmask], 1u);
    }
    __syncthreads();
    for (int i = threadIdx.x; i < 2048; i += blockDim.x)
        if (sb[i]) atomicAdd(&g_bins[i], sb[i]);

    if (ff_last_block_n(2, gridDim.x)) {
        if (threadIdx.x == 0) {
            int nbins = (int)binmask + 1;
            long long r = g_rank;
            long long cum = 0;
            int sel = nbins - 1;
            for (int b = 0; b < nbins; b++) {
                unsigned c = g_bins[b];
                if (cum + (long long)c > r) { sel = b; r = r - cum; break; }
                cum += c;
            }
            unsigned np = g_prefix | ((unsigned)sel << shift);
            if (is_final) {
                float amax = fmaxf(__uint_as_float(np), 1e-5f);
                g_s[0] = 127.0f / amax;
            } else {
                g_prefix   = np;
                g_prefmask = g_prefmask | (binmask << shift);
                g_rank     = r;
            }
            g_ctr[2] = 0u;
        }
        __syncthreads();
        for (int i = threadIdx.x; i < 2048; i += blockDim.x) g_bins[i] = 0u;
    }
}

// ---------------- layer-1 activation quantize -> bf16 ints ----------------
__global__ __launch_bounds__(256) void ff_actquant1(long long n4) {
    float s = g_s[0];
    const float4* in = (const float4*)(const float*)g_h1;
    uint2* out = (uint2*)g_h1q;
    long long stride = (long long)gridDim.x * blockDim.x;
    for (long long i = (long long)blockIdx.x * blockDim.x + threadIdx.x; i < n4; i += stride) {
        float4 v = in[i];
        float q0 = fminf(fmaxf(rintf(v.x * s), -128.0f), 127.0f);
        float q1 = fminf(fmaxf(rintf(v.y * s), -128.0f), 127.0f);
        float q2 = fminf(fmaxf(rintf(v.z * s), -128.0f), 127.0f);
        float q3 = fminf(fmaxf(rintf(v.w * s), -128.0f), 127.0f);
        uint2 o;
        o.x = ff_pack_bf16(q0, q1);
        o.y = ff_pack_bf16(q2, q3);
        out[i] = o;
    }
}

// ---------------- bf16 tensor-core GEMM, 4-stage cp.async pipeline ----------------
#define GSTG 16384
#define GSMEM (4 * GSTG)

DEV void ff_load_stage(const __nv_bfloat16* A, const __nv_bfloat16* Bw, int K,
                       int bm, int bn, int kt, unsigned char* sa, int tid)
{
    unsigned char* sb = sa + 8192;
    #pragma unroll
    for (int i = 0; i < 2; i++) {
        int c = tid + i * 256;
        int row = c >> 2, ch = c & 3;
        int sw = ch ^ ((row >> 1) & 3);
        ff_cp_async16(sa + (row * 4 + sw) * 16, A  + (size_t)(bm + row) * K + kt * 32 + ch * 8);
        ff_cp_async16(sb + (row * 4 + sw) * 16, Bw + (size_t)(bn + row) * K + kt * 32 + ch * 8);
    }
    asm volatile("cp.async.commit_group;\n");
}

template<int LAYER>
__global__ __launch_bounds__(256, 2) void ff_gemm(float* __restrict__ Cext)
{
    constexpr int KD = LAYER ? HDIM : DDIM;
    constexpr int ND = LAYER ? DDIM : HDIM;
    constexpr int KT = KD >> 5;
    const __nv_bfloat16* A  = LAYER ? g_a2q : g_h1q;
    const __nv_bfloat16* Bw = LAYER ? g_w2q : g_w1q;

    extern __shared__ __align__(128) unsigned char smem[];
    const int tid  = threadIdx.x;
    const int lane = tid & 31, warp = tid >> 5;
    const int wm = warp >> 2, wn = warp & 3;     // 2 x 4 warp grid
    const int bm = blockIdx.y * 128, bn = blockIdx.x * 128;   // N on x (L2 reuse)

    float acc[4][4][4];
    #pragma unroll
    for (int a = 0; a < 4; a++)
        #pragma unroll
        for (int b = 0; b < 4; b++)
            #pragma unroll
            for (int c = 0; c < 4; c++) acc[a][b][c] = 0.0f;

    ff_load_stage(A, Bw, KD, bm, bn, 0, smem + 0 * GSTG, tid);
    ff_load_stage(A, Bw, KD, bm, bn, 1, smem + 1 * GSTG, tid);
    ff_load_stage(A, Bw, KD, bm, bn, 2, smem + 2 * GSTG, tid);

    for (int kt = 0; kt < KT; kt++) {
        if (kt < KT - 2)       asm volatile("cp.async.wait_group 2;\n" ::: "memory");
        else if (kt == KT - 2) asm volatile("cp.async.wait_group 1;\n" ::: "memory");
        else                   asm volatile("cp.async.wait_group 0;\n" ::: "memory");
        __syncthreads();
        if (kt + 3 < KT)
            ff_load_stage(A, Bw, KD, bm, bn, kt + 3, smem + ((kt + 3) & 3) * GSTG, tid);

        unsigned char* sa = smem + (kt & 3) * GSTG;
        unsigned char* sb = sa + 8192;

        #pragma unroll
        for (int s = 0; s < 2; s++) {
            unsigned ar[4][4];
            #pragma unroll
            for (int mi = 0; mi < 4; mi++) {
                int row = wm * 64 + mi * 16 + ((lane >> 3) & 1) * 8 + (lane & 7);
                int ch  = (2 * s + (lane >> 4)) ^ ((row >> 1) & 3);
                unsigned addr = (unsigned)__cvta_generic_to_shared(sa + (row * 4 + ch) * 16);
                asm volatile("ldmatrix.sync.aligned.m8n8.x4.shared.b16 {%0,%1,%2,%3}, [%4];\n"
                    : "=r"(ar[mi][0]), "=r"(ar[mi][1]), "=r"(ar[mi][2]), "=r"(ar[mi][3])
                    : "r"(addr));
            }
            unsigned br[4][2];
            #pragma unroll
            for (int nj2 = 0; nj2 < 2; nj2++) {
                int row = wn * 32 + nj2 * 16 + ((lane >> 3) & 1) * 8 + (lane & 7);
                int ch  = (2 * s + (lane >> 4)) ^ ((row >> 1) & 3);
                unsigned addr = (unsigned)__cvta_generic_to_shared(sb + (row * 4 + ch) * 16);
                unsigned q0, q1, q2, q3;
                asm volatile("ldmatrix.sync.aligned.m8n8.x4.shared.b16 {%0,%1,%2,%3}, [%4];\n"
                    : "=r"(q0), "=r"(q1), "=r"(q2), "=r"(q3) : "r"(addr));
                br[2 * nj2][0] = q0;     br[2 * nj2][1] = q2;
                br[2 * nj2 + 1][0] = q1; br[2 * nj2 + 1][1] = q3;
            }
            #pragma unroll
            for (int mi = 0; mi < 4; mi++)
                #pragma unroll
                for (int nj = 0; nj < 4; nj++) {
                    asm volatile(
                        "mma.sync.aligned.m16n8k16.row.col.f32.bf16.bf16.f32 "
                        "{%0,%1,%2,%3},{%4,%5,%6,%7},{%8,%9},{%0,%1,%2,%3};\n"
                        : "+f"(acc[mi][nj][0]), "+f"(acc[mi][nj][1]),
                          "+f"(acc[mi][nj][2]), "+f"(acc[mi][nj][3])
                        : "r"(ar[mi][0]), "r"(ar[mi][1]), "r"(ar[mi][2]), "r"(ar[mi][3]),
                          "r"(br[nj][0]), "r"(br[nj][1]));
                }
        }
    }

    if (LAYER == 0) {
        #pragma unroll
        for (int mi = 0; mi < 4; mi++) {
            int r0 = bm + wm * 64 + mi * 16 + (lane >> 2);
            #pragma unroll
            for (int nj = 0; nj < 4; nj++) {
                int cc = bn + wn * 32 + nj * 8 + (lane & 3) * 2;
                int c0 = min(max((int)acc[mi][nj][0], -32768), 32767);
                int c1 = min(max((int)acc[mi][nj][1], -32768), 32767);
                int c2 = min(max((int)acc[mi][nj][2], -32768), 32767);
                int c3 = min(max((int)acc[mi][nj][3], -32768), 32767);
                *(unsigned*)(g_n2 + (size_t)r0 * ND + cc) =
                    ((unsigned)(unsigned short)(short)c0) | (((unsigned)(unsigned short)(short)c1) << 16);
                *(unsigned*)(g_n2 + (size_t)(r0 + 8) * ND + cc) =
                    ((unsigned)(unsigned short)(short)c2) | (((unsigned)(unsigned short)(short)c3) << 16);
            }
        }
    } else {
        float sc = g_gamma[1] / g_s[1];
        #pragma unroll
        for (int mi = 0; mi < 4; mi++) {
            int r0 = bm + wm * 64 + mi * 16 + (lane >> 2);
            #pragma unroll
            for (int nj = 0; nj < 4; nj++) {
                int cc = bn + wn * 32 + nj * 8 + (lane & 3) * 2;
                float2 p0 = make_float2(acc[mi][nj][0] * sc, acc[mi][nj][1] * sc);
                float2 p1 = make_float2(acc[mi][nj][2] * sc, acc[mi][nj][3] * sc);
                *(float2*)(Cext + (size_t)r0 * ND + cc) = p0;
                *(float2*)(Cext + (size_t)(r0 + 8) * ND + cc) = p1;
            }
        }
    }
}

// ---------------- layer-2 integer histogram + fused quantile scan ----------------
__global__ __launch_bounds__(256) void ff_hist2_scan(long long n8) {
    __shared__ unsigned sb[8192];                           // core range [-4096, 4095]
    for (int i = threadIdx.x; i < 8192; i += blockDim.x) sb[i] = 0u;
    __syncthreads();
    const uint4* p = (const uint4*)g_n2;
    long long stride = (long long)gridDim.x * blockDim.x;
    long long base = (long long)blockIdx.x * blockDim.x + threadIdx.x;
    for (long long i = base; i < n8; i += 2 * stride) {
        uint4 v0 = p[i];
        bool has2 = (i + stride) < n8;
        uint4 v1 = has2 ? p[i + stride] : make_uint4(0, 0, 0, 0);
        unsigned ww[8] = {v0.x, v0.y, v0.z, v0.w, v1.x, v1.y, v1.z, v1.w};
        int cnt = has2 ? 8 : 4;
        #pragma unroll
        for (int j = 0; j < 8; j++) {
            if (j >= cnt) break;
            int n0 = (int)(short)(ww[j] & 0xffffu);
            int n1 = (int)(short)(ww[j] >> 16);
            int b0 = n0 + 4096, b1 = n1 + 4096;
            if ((unsigned)b0 < 8192u) atomicAdd(&sb[b0], 1u); else atomicAdd(&g_hist2[n0 + 32768], 1u);
            if ((unsigned)b1 < 8192u) atomicAdd(&sb[b1], 1u); else atomicAdd(&g_hist2[n1 + 32768], 1u);
        }
    }
    __syncthreads();
    for (int i = threadIdx.x; i < 8192; i += blockDim.x)
        if (sb[i]) atomicAdd(&g_hist2[i + (32768 - 4096)], sb[i]);

    if (ff_last_block_n(3, gridDim.x)) {
        __shared__ long long partial[256];
        int t = threadIdx.x;
        long long c = 0;
        for (int b = t * 256; b < (t + 1) * 256; b++) c += (long long)g_hist2[b];
        partial[t] = c;
        __syncthreads();
        if (t == 0) {
            double idx = 0.995 * (double)(N2 - 1);
            long long k = (long long)idx;
            double f = idx - (double)k;
            long long cum = 0;
            int chunk = 0;
            for (; chunk < 256; chunk++) {
                if (cum + partial[chunk] > k) break;
                cum += partial[chunk];
            }
            long long r = k - cum;
            int nk = 0, nk1 = 0;
            int b = chunk * 256;
            for (;; b++) {
                long long cc = (long long)g_hist2[b];
                if (r < cc) {
                    nk = b - 32768;
                    if (r + 1 < cc) nk1 = nk;
                    else {
                        int b2 = b + 1;
                        while (b2 < 65536 && g_hist2[b2] == 0u) b2++;
                        nk1 = (b2 < 65536) ? (b2 - 32768) : nk;
                    }
                    break;
                }
                r -= cc;
            }
            float sc1 = g_gamma[0] / g_s[0];
            float v0 = ff_gelu(sc1 * (float)nk);
            float v1 = ff_gelu(sc1 * (float)nk1);
            float amax = fmaxf((float)((1.0 - f) * (double)v0 + f * (double)v1), 1e-5f);
            g_s[1] = 127.0f / amax;
            g_sc1 = sc1;
            g_ctr[3] = 0u;
        }
    }
}

// ---------------- LUT build (+ re-zero hist2 for next replay) ----------------
__global__ void ff_lut_build() {
    int i = blockIdx.x * blockDim.x + threadIdx.x;   // 65536
    int n = i - 32768;
    float g = ff_gelu(g_sc1 * (float)n);
    float q = fminf(fmaxf(rintf(g * g_s[1]), -128.0f), 127.0f);
    __nv_bfloat16 b = __float2bfloat16(q);           // exact (integer <= 128)
    g_lut[i] = *reinterpret_cast<unsigned short*>(&b);
    g_hist2[i] = 0u;                                  // reset for next graph replay
}

// ---------------- layer-2 quantize via LUT gather -> bf16 ----------------
__global__ __launch_bounds__(256) void ff_actquant2(long long n8) {
    const uint4* in = (const uint4*)g_n2;
    uint4* out = (uint4*)g_a2q;
    const unsigned short* lut = g_lut;
    long long stride = (long long)gridDim.x * blockDim.x;
    long long base = (long long)blockIdx.x * blockDim.x + threadIdx.x;
    for (long long i = base; i < n8; i += 2 * stride) {
        uint4 v0 = in[i];
        unsigned o0[4];
        #pragma unroll
        for (int j = 0; j < 4; j++) {
            unsigned wj = (&v0.x)[j];
            unsigned lo = lut[(wj & 0xffffu) ^ 0x8000u];
            unsigned hi = lut[(wj >> 16) ^ 0x8000u];
            o0[j] = lo | (hi << 16);
        }
        out[i] = make_uint4(o0[0], o0[1], o0[2], o0[3]);
        if (i + stride < n8) {
            uint4 v1 = in[i + stride];
            unsigned o1[4];
            #pragma unroll
            for (int j = 0; j < 4; j++) {
                unsigned wj = (&v1.x)[j];
                unsigned lo = lut[(wj & 0xffffu) ^ 0x8000u];
                unsigned hi = lut[(wj >> 16) ^ 0x8000u];
                o1[j] = lo | (hi << 16);
            }
            out[i + stride] = make_uint4(o1[0], o1[1], o1[2], o1[3]);
        }
    }
}

// ---------------- launch ----------------
extern "C" void kernel_launch(void* const* d_in, const int* in_sizes, int n_in,
                              void* d_out, int out_size)
{
    const float* x    = (const float*)d_in[0];
    const float* ln_g = (const float*)d_in[1];
    const float* ln_b = (const float*)d_in[2];
    const float* w1   = (const float*)d_in[3];
    const float* w2   = (const float*)d_in[4];
    float* out = (float*)d_out;

    cudaFuncSetAttribute(ff_gemm<0>, cudaFuncAttributeMaxDynamicSharedMemorySize, GSMEM);
    cudaFuncSetAttribute(ff_gemm<1>, cudaFuncAttributeMaxDynamicSharedMemorySize, GSMEM);

    // LayerNorm (with fused level-0 histogram)
    ff_ln_kernel<<<MM, 256>>>(x, ln_g, ln_b);

    // Both weight gammas in one launch, then both quantizes in one launch
    ff_wabs2<<<2048, 256>>>(w1, w2);
    ff_wquant2<<<4096, 256>>>(w1, w2);

    // Layer-1 quantile: level-0 scan (hist was fused into LN), then levels 1,2
    ff_scan0<<<1, 256>>>();
    ff_hist_scan<<<2048, 256>>>(N1 / 4, 10, 2047u, 0);
    ff_hist_scan<<<2048, 256>>>(N1 / 4, 0, 1023u, 1);

    // Quantize acts #1 -> bf16 ints
    ff_actquant1<<<4096, 256>>>(N1 / 4);

    // GEMM1 (bf16 tensor cores, 4-stage) -> exact i16 integers
    ff_gemm<0><<<dim3(HDIM / 128, MM / 128), 256, GSMEM>>>(nullptr);

    // Layer-2 quantile: integer histogram + fused scan
    ff_hist2_scan<<<512, 256>>>(N2 / 8);
    ff_lut_build<<<256, 256>>>();

    // GELU + quantize acts #2 via LUT -> bf16 ints
    ff_actquant2<<<4096, 256>>>(N2 / 8);

    // GEMM2 (bf16 tensor cores, 4-stage) -> fp32 output
    ff_gemm<1><<<dim3(DDIM / 128, MM / 128), 256, GSMEM>>>(out);
}